// round 12
// baseline (speedup 1.0000x reference)
#include <cuda_runtime.h>
#include <cfloat>

// Symmetric squared-Hausdorff per batch — 3-launch exact pruning (R12).
// d^2(p,g) = |p|^2 + s, s = |g|^2 - 2 p.g (|p|^2 added after the min).
//
// K1 (hd_pack): grid (B,2,4): packs 1024 pts/block -> g_pack[arr][b][j] =
//     (-2g,|g|^2); per-chunk radius-argmax candidate -> g_candpart.
// K2 (hd_p1): reduces the 4 chunk candidates; LB = exact min-d^2 of the
//     candidate over the full opposite pack (L2) minus margin; branchless
//     f32x2 scan of the first 128 inner pts for all points; certified
//     (partial < LB) -> one atomicMax/block; uncertified -> global list.
// K3 (hd_tail): 16384 warps grid-stride the list; one point/warp over the
//     remaining 3968 inner pts: one 128-pt half round ([128,256), vote),
//     then 15 full 256-pt rounds ([256,4096), divides evenly — no OOB);
//     exact values atomicMax'ed; last block (ticket) writes out[].
//
// Exactness: certified partials lie in [true, LB) and cannot win the max;
// the argmax never certifies and its exact min is computed from identically-
// evaluated per-pair values (min/max order-independent -> deterministic).

#define BATCH   16
#define NPTS    4096
#define PCH     4                    // pack chunks per (arr,b)
#define TP      256                  // pack threads (1024 pts / block)
#define T2      512
#define OPT     2
#define PTSBLK  (T2 * OPT)           // 1024
#define OCH     (NPTS / PTSBLK)      // 4
#define P1PTS   128                  // phase-1 inner points
#define P1SLOTS (P1PTS / 2)          // 64 packed pair-slots
#define T3      256
#define GRID3   2048                 // 16384 warps
#define VC      8                    // tail lane-iters per full vote round
#define TAIL0   256                  // start of the evenly-divisible region

__device__ float4       g_pack[2][BATCH][NPTS];     // (-2gx,-2gy,-2gz,|g|^2)
__device__ float4       g_candpart[2][BATCH][PCH];  // (cx,cy,cz,|c|^2)
__device__ float        g_lb[2][BATCH];
__device__ int2         g_list[2 * BATCH * NPTS];   // (code, partial bits)
__device__ int          g_cnt;
__device__ unsigned int g_done;
__device__ unsigned int g_bmax_u[2][BATCH];         // monotonic-encoded max

typedef unsigned long long u64t;

__device__ __forceinline__ u64t fma2(u64t a, u64t b, u64t c) {
    u64t d;
    asm("fma.rn.f32x2 %0, %1, %2, %3;" : "=l"(d) : "l"(a), "l"(b), "l"(c));
    return d;
}
__device__ __forceinline__ u64t pk(float lo, float hi) {
    u64t d;
    asm("mov.b64 %0, {%1, %2};" : "=l"(d) : "f"(lo), "f"(hi));
    return d;
}
__device__ __forceinline__ float2 upk(u64t v) {
    float2 r;
    asm("mov.b64 {%0, %1}, %2;" : "=f"(r.x), "=f"(r.y) : "l"(v));
    return r;
}
// monotonic float<->uint (total order preserved under unsigned compare)
__device__ __forceinline__ unsigned int encf(float v) {
    unsigned int b = __float_as_uint(v);
    return (b & 0x80000000u) ? ~b : (b | 0x80000000u);
}
__device__ __forceinline__ float decf(unsigned int u) {
    unsigned int b = (u & 0x80000000u) ? (u & 0x7fffffffu) : ~u;
    return __uint_as_float(b);
}

// ---------------- K1: pack 1024 pts/block + chunk candidate ----------------
__global__ void __launch_bounds__(TP)
hd_pack(const float* __restrict__ preds, const float* __restrict__ gts) {
    const int b = blockIdx.x, arr = blockIdx.y, ch = blockIdx.z;
    const float* __restrict__ src = (arr == 0 ? preds : gts) + (size_t)b * NPTS * 3;
    const int tid = threadIdx.x;
    const int base = ch * (NPTS / PCH);              // 1024 pts per chunk

    if (tid == 0 && ch == 0) {
        g_bmax_u[arr][b] = 0u;                       // < any encoded float
        if (b == 0 && arr == 0) { g_cnt = 0; g_done = 0u; }
    }

    float4* packp = &g_pack[arr][b][0];
    float bestr = -1.0f; int besti = 0;
#pragma unroll
    for (int k = 0; k < NPTS / PCH / TP; k++) {      // 4 points/thread
        int j = base + tid + k * TP;
        float gx = src[3*j], gy = src[3*j+1], gz = src[3*j+2];
        float w  = fmaf(gx, gx, fmaf(gy, gy, gz * gz));
        packp[j] = make_float4(-2.0f*gx, -2.0f*gy, -2.0f*gz, w);
        if (w > bestr || (w == bestr && j < besti)) { bestr = w; besti = j; }
    }
#pragma unroll
    for (int off = 16; off; off >>= 1) {
        float r2 = __shfl_xor_sync(0xffffffffu, bestr, off);
        int   i2 = __shfl_xor_sync(0xffffffffu, besti, off);
        if (r2 > bestr || (r2 == bestr && i2 < besti)) { bestr = r2; besti = i2; }
    }
    __shared__ float sr[TP/32]; __shared__ int si[TP/32];
    if ((tid & 31) == 0) { sr[tid>>5] = bestr; si[tid>>5] = besti; }
    __syncthreads();
    if (tid == 0) {
        float r = sr[0]; int i = si[0];
#pragma unroll
        for (int w = 1; w < TP/32; w++)
            if (sr[w] > r || (sr[w] == r && si[w] < i)) { r = sr[w]; i = si[w]; }
        g_candpart[arr][b][ch] = make_float4(src[3*i], src[3*i+1], src[3*i+2], r);
    }
}

// ---------------- K2: candidate reduce + LB + branchless phase-1 ------------
__global__ void __launch_bounds__(T2)
hd_p1(const float* __restrict__ preds, const float* __restrict__ gts) {
    __shared__ __align__(16) ulonglong2 shv[P1SLOTS * 2];   // 2 KB
    __shared__ float s_red[T2 / 32];
    __shared__ float s_lb;

    const int och = blockIdx.x, b = blockIdx.y, dir = blockIdx.z;
    const float* __restrict__ outer = (dir == 0 ? preds : gts) + (size_t)b * NPTS * 3;
    const float* __restrict__ inner = (dir == 0 ? gts : preds) + (size_t)b * NPTS * 3;
    const float4* __restrict__ packp = &g_pack[dir ^ 1][b][0];   // inner pack
    const int tid = threadIdx.x;

    // stage first P1SLOTS pairs: {-2x0,-2x1,-2y0,-2y1},{-2z0,-2z1,w0,w1}
    if (tid < P1SLOTS) {
        const float* gp = inner + (size_t)tid * 6;
        float x0 = gp[0], y0 = gp[1], z0 = gp[2];
        float x1 = gp[3], y1 = gp[4], z1 = gp[5];
        ((float4*)shv)[tid * 2 + 0] = make_float4(-2.f*x0, -2.f*x1, -2.f*y0, -2.f*y1);
        ((float4*)shv)[tid * 2 + 1] = make_float4(-2.f*z0, -2.f*z1,
                                fmaf(x0, x0, fmaf(y0, y0, z0*z0)),
                                fmaf(x1, x1, fmaf(y1, y1, z1*z1)));
    }

    // reduce the 4 chunk candidates (ascending scan + strict '>' is
    // deterministic: ties resolve to the lowest chunk / lowest index)
    float4 cand = g_candpart[dir][b][0];
#pragma unroll
    for (int c = 1; c < PCH; c++) {
        float4 q = g_candpart[dir][b][c];
        if (q.w > cand.w) cand = q;
    }

    const int gbase = och * PTSBLK;
    u64t px2[OPT], py2[OPT], pz2[OPT];
    float rq[OPT], mn[OPT];
#pragma unroll
    for (int o = 0; o < OPT; o++) {
        int i = gbase + o * T2 + tid;
        float x = outer[3*i], y = outer[3*i+1], z = outer[3*i+2];
        px2[o] = pk(x, x); py2[o] = pk(y, y); pz2[o] = pk(z, z);
        rq[o]  = fmaf(x, x, fmaf(y, y, z*z));
        mn[o]  = FLT_MAX;
    }

    // LB part 1: this thread's share of candidate-vs-all-inner (8 evals)
    float cm = FLT_MAX;
#pragma unroll
    for (int k = 0; k < NPTS / T2; k++) {
        float4 p = packp[tid + k * T2];
        float t = fmaf(p.x, cand.x, p.w);
        t = fmaf(p.y, cand.y, t);
        t = fmaf(p.z, cand.z, t);
        cm = fminf(cm, t);
    }
    __syncthreads();                                  // staging visible

    // main branchless phase-1 loop (64 slots)
#pragma unroll 8
    for (int s = 0; s < P1SLOTS; s++) {
        ulonglong2 ab = shv[s * 2 + 0];
        ulonglong2 cd = shv[s * 2 + 1];
#pragma unroll
        for (int o = 0; o < OPT; o++) {
            u64t t = fma2(ab.x, px2[o], cd.y);
            t = fma2(ab.y, py2[o], t);
            t = fma2(cd.x, pz2[o], t);
            float2 tv = upk(t);
            mn[o] = fminf(mn[o], fminf(tv.x, tv.y));
        }
    }

    // LB part 2: reduce candidate min -> LB with margin
#pragma unroll
    for (int off = 16; off; off >>= 1)
        cm = fminf(cm, __shfl_xor_sync(0xffffffffu, cm, off));
    if ((tid & 31) == 0) s_red[tid >> 5] = cm;
    __syncthreads();
    if (tid == 0) {
        float m = s_red[0];
#pragma unroll
        for (int w = 1; w < T2 / 32; w++) m = fminf(m, s_red[w]);
        float lb = m + cand.w;
        s_lb = lb - fabsf(lb) * 1e-5f - 1e-12f;
        if (och == 0) g_lb[dir][b] = s_lb;           // identical in all blocks
    }
    __syncthreads();

    // filter: certified -> block max; uncertified -> global list
    const float lbm = s_lb;
    float cmax = -FLT_MAX;
#pragma unroll
    for (int o = 0; o < OPT; o++) {
        int gi = gbase + o * T2 + tid;
        float v = mn[o] + rq[o];
        if (v < lbm) {
            cmax = fmaxf(cmax, v);
        } else {
            int k = atomicAdd(&g_cnt, 1);
            g_list[k] = make_int2((dir << 16) | (b << 12) | gi,
                                  __float_as_int(v));
        }
    }
#pragma unroll
    for (int off = 16; off; off >>= 1)
        cmax = fmaxf(cmax, __shfl_xor_sync(0xffffffffu, cmax, off));
    if ((tid & 31) == 0) s_red[tid >> 5] = cmax;
    __syncthreads();
    if (tid == 0) {
        float m = s_red[0];
#pragma unroll
        for (int w = 1; w < T2 / 32; w++) m = fmaxf(m, s_red[w]);
        atomicMax(&g_bmax_u[dir][b], encf(m));
    }
}

// ---------------- K3: warp-per-point tail + fused final ----------------
__global__ void __launch_bounds__(T3)
hd_tail(const float* __restrict__ preds, const float* __restrict__ gts,
        float* __restrict__ out) {
    __shared__ bool s_last;
    const int tid  = threadIdx.x;
    const int lane = tid & 31;
    const int wgid = blockIdx.x * (T3 / 32) + (tid >> 5);
    const int cnt  = g_cnt;

    for (int u = wgid; u < cnt; u += GRID3 * (T3 / 32)) {
        const int2 e = g_list[u];
        const int code = e.x;
        const float partial = __int_as_float(e.y);
        const int gi = code & 4095, b = (code >> 12) & 15, dir = code >> 16;
        const float* __restrict__ outer = (dir == 0 ? preds : gts) + (size_t)b * NPTS * 3;

        const float x = outer[3*gi], y = outer[3*gi+1], z = outer[3*gi+2];
        const float rq = fmaf(x, x, fmaf(y, y, z*z));
        const float thr = g_lb[dir][b] - rq;         // s-domain threshold
        const float4* packp = &g_pack[dir ^ 1][b][0];

        float m = FLT_MAX;
        bool done = false;

        // half round: inner points [P1PTS, TAIL0) = 128 pts (4 lane-iters)
#pragma unroll
        for (int k = 0; k < (TAIL0 - P1PTS) / 32; k++) {
            float4 p = packp[P1PTS + k * 32 + lane];
            float t = fmaf(p.x, x, p.w);
            t = fmaf(p.y, y, t);
            t = fmaf(p.z, z, t);
            m = fminf(m, t);
        }
        done = __any_sync(0xffffffffu, m < thr);

        // full rounds: [TAIL0, NPTS) = 3840 pts, 15 rounds of 256 (no OOB)
        if (!done) {
            for (int base = TAIL0; base < NPTS; base += 32 * VC) {
#pragma unroll
                for (int k = 0; k < VC; k++) {
                    float4 p = packp[base + k * 32 + lane];
                    float t = fmaf(p.x, x, p.w);
                    t = fmaf(p.y, y, t);
                    t = fmaf(p.z, z, t);
                    m = fminf(m, t);
                }
                if (__any_sync(0xffffffffu, m < thr)) break;   // certified
            }
        }
#pragma unroll
        for (int off = 16; off; off >>= 1)
            m = fminf(m, __shfl_xor_sync(0xffffffffu, m, off));
        if (lane == 0)
            atomicMax(&g_bmax_u[dir][b], encf(fminf(partial, m + rq)));
    }

    // fused final: last block to finish writes out[]
    __syncthreads();
    if (tid == 0) {
        __threadfence();
        unsigned int ticket = atomicAdd(&g_done, 1u);
        s_last = (ticket == GRID3 - 1);
    }
    __syncthreads();
    if (s_last && tid < BATCH) {
        float l2 = decf(__ldcg(&g_bmax_u[0][tid]));
        float l1 = decf(__ldcg(&g_bmax_u[1][tid]));
        out[tid] = 0.5f * (l1 + l2);
    }
}

extern "C" void kernel_launch(void* const* d_in, const int* in_sizes, int n_in,
                              void* d_out, int out_size) {
    const float* preds = (const float*)d_in[0];
    const float* gts   = (const float*)d_in[1];
    float* out = (float*)d_out;

    hd_pack<<<dim3(BATCH, 2, PCH), TP>>>(preds, gts);
    hd_p1  <<<dim3(OCH, BATCH, 2), T2>>>(preds, gts);
    hd_tail<<<GRID3, T3>>>(preds, gts, out);
}

// round 13
// speedup vs baseline: 1.1276x; 1.1276x over previous
#include <cuda_runtime.h>
#include <cfloat>

// Symmetric squared-Hausdorff per batch — SINGLE persistent kernel (R13).
// d^2(p,g) = |p|^2 + s, s = |g|^2 - 2 p.g (|p|^2 added after the min).
//
// Grid = 128 blocks x 512 threads (<= 148 SMs, 1 block/SM => all co-resident).
// Phase A: pack both arrays -> g_pack[arr][b][j]=(-2g,|g|^2), per-chunk
//          radius-argmax candidates, counter resets.          [barrier]
// Phase B: per (och,b,dir): reduce 4 chunk candidates; LB = exact min-d^2 of
//          candidate over full opposite pack minus margin; branchless f32x2
//          scan of first 256 inner pts; certified -> block max atomicMax;
//          uncertified -> global list.                        [barrier]
// Phase C: 2048 warps grid-stride the list; one point/warp over remaining
//          3840 inner pts (15 x 256-pt vote rounds, divides evenly);
//          exact values atomicMax'ed.                         [barrier]
//          Block 0 writes out[16].
//
// Barriers: generation-counting (ctr monotonic, gen = old/128; spin until
// ctr/128 != gen) — no reset, safe across graph replays. Every thread
// __threadfence()s before arrival => producer writes visible after barrier.
//
// Exactness: certified partials lie in [true, LB) and cannot win the max;
// the argmax never certifies and its exact min is computed from identically-
// evaluated per-pair values (min/max order-independent -> deterministic).

#define BATCH   16
#define NPTS    4096
#define NBLK    128
#define T       512
#define PCH     4                    // pack chunks per (arr,b)
#define OPT     2
#define PTSBLK  (T * OPT)            // 1024 outer pts per phase-B block
#define OCH     (NPTS / PTSBLK)      // 4
#define P1PTS   256                  // phase-1 inner points
#define P1SLOTS (P1PTS / 2)          // 128 packed pair-slots
#define VC      8                    // tail lane-iters per vote round (256 pts)

__device__ float4       g_pack[2][BATCH][NPTS];     // (-2gx,-2gy,-2gz,|g|^2)
__device__ float4       g_candpart[2][BATCH][PCH];  // (cx,cy,cz,|c|^2)
__device__ float        g_lb[2][BATCH];
__device__ int2         g_list[2 * BATCH * NPTS];   // (code, partial bits)
__device__ int          g_cnt;
__device__ unsigned int g_bar[3];                   // generation barriers
__device__ unsigned int g_bmax_u[2][BATCH];         // monotonic-encoded max

typedef unsigned long long u64t;

__device__ __forceinline__ u64t fma2(u64t a, u64t b, u64t c) {
    u64t d;
    asm("fma.rn.f32x2 %0, %1, %2, %3;" : "=l"(d) : "l"(a), "l"(b), "l"(c));
    return d;
}
__device__ __forceinline__ u64t pk(float lo, float hi) {
    u64t d;
    asm("mov.b64 %0, {%1, %2};" : "=l"(d) : "f"(lo), "f"(hi));
    return d;
}
__device__ __forceinline__ float2 upk(u64t v) {
    float2 r;
    asm("mov.b64 {%0, %1}, %2;" : "=f"(r.x), "=f"(r.y) : "l"(v));
    return r;
}
// monotonic float<->uint (total order preserved under unsigned compare)
__device__ __forceinline__ unsigned int encf(float v) {
    unsigned int b = __float_as_uint(v);
    return (b & 0x80000000u) ? ~b : (b | 0x80000000u);
}
__device__ __forceinline__ float decf(unsigned int u) {
    unsigned int b = (u & 0x80000000u) ? (u & 0x7fffffffu) : ~u;
    return __uint_as_float(b);
}

// generation-counting grid barrier (all NBLK blocks co-resident)
__device__ __forceinline__ void gbar(int which) {
    __threadfence();                     // order this thread's prior writes
    __syncthreads();                     // all threads of block fenced
    if (threadIdx.x == 0) {
        unsigned int gen = atomicAdd(&g_bar[which], 1u) / NBLK;
        while (atomicAdd(&g_bar[which], 0u) / NBLK == gen) { }
    }
    __syncthreads();
}

__global__ void __launch_bounds__(T, 1)
hd_fused(const float* __restrict__ preds, const float* __restrict__ gts,
         float* __restrict__ out) {
    __shared__ __align__(16) ulonglong2 shv[P1SLOTS * 2];   // 4 KB
    __shared__ float s_red[T / 32];
    __shared__ int   s_redi[T / 32];
    __shared__ float s_lb;

    const int bid = blockIdx.x;
    const int tid = threadIdx.x;
    const int lane = tid & 31;

    // ================= Phase A: pack + chunk candidates + resets ===========
    {
        const int arr = bid >> 6, b = (bid >> 2) & 15, ch = bid & 3;
        const float* __restrict__ src = (arr == 0 ? preds : gts) + (size_t)b * NPTS * 3;
        const int base = ch * (NPTS / PCH);          // 1024 pts / block

        if (tid == 0 && ch == 0) {
            g_bmax_u[arr][b] = 0u;
            if (bid == 0) g_cnt = 0;
        }

        float4* packp = &g_pack[arr][b][0];
        float bestr = -1.0f; int besti = 0;
#pragma unroll
        for (int k = 0; k < NPTS / PCH / T; k++) {   // 2 points/thread
            int j = base + tid + k * T;
            float gx = src[3*j], gy = src[3*j+1], gz = src[3*j+2];
            float w  = fmaf(gx, gx, fmaf(gy, gy, gz * gz));
            packp[j] = make_float4(-2.0f*gx, -2.0f*gy, -2.0f*gz, w);
            if (w > bestr || (w == bestr && j < besti)) { bestr = w; besti = j; }
        }
#pragma unroll
        for (int off = 16; off; off >>= 1) {
            float r2 = __shfl_xor_sync(0xffffffffu, bestr, off);
            int   i2 = __shfl_xor_sync(0xffffffffu, besti, off);
            if (r2 > bestr || (r2 == bestr && i2 < besti)) { bestr = r2; besti = i2; }
        }
        if ((tid & 31) == 0) { s_red[tid>>5] = bestr; s_redi[tid>>5] = besti; }
        __syncthreads();
        if (tid == 0) {
            float r = s_red[0]; int i = s_redi[0];
#pragma unroll
            for (int w = 1; w < T/32; w++)
                if (s_red[w] > r || (s_red[w] == r && s_redi[w] < i)) { r = s_red[w]; i = s_redi[w]; }
            g_candpart[arr][b][ch] = make_float4(src[3*i], src[3*i+1], src[3*i+2], r);
        }
        __syncthreads();
    }
    gbar(0);

    // ================= Phase B: LB + branchless p1 + filter =================
    {
        const int dir = bid >> 6, b = (bid >> 2) & 15, och = bid & 3;
        const float* __restrict__ outer = (dir == 0 ? preds : gts) + (size_t)b * NPTS * 3;
        const float* __restrict__ inner = (dir == 0 ? gts : preds) + (size_t)b * NPTS * 3;
        const float4* __restrict__ packp = &g_pack[dir ^ 1][b][0];

        // stage first P1SLOTS pairs
        if (tid < P1SLOTS) {
            const float* gp = inner + (size_t)tid * 6;
            float x0 = gp[0], y0 = gp[1], z0 = gp[2];
            float x1 = gp[3], y1 = gp[4], z1 = gp[5];
            ((float4*)shv)[tid * 2 + 0] = make_float4(-2.f*x0, -2.f*x1, -2.f*y0, -2.f*y1);
            ((float4*)shv)[tid * 2 + 1] = make_float4(-2.f*z0, -2.f*z1,
                                    fmaf(x0, x0, fmaf(y0, y0, z0*z0)),
                                    fmaf(x1, x1, fmaf(y1, y1, z1*z1)));
        }

        // candidate = best of 4 chunk candidates (deterministic ascending scan)
        float4 cand = g_candpart[dir][b][0];
#pragma unroll
        for (int c = 1; c < PCH; c++) {
            float4 q = g_candpart[dir][b][c];
            if (q.w > cand.w) cand = q;
        }

        const int gbase = och * PTSBLK;
        u64t px2[OPT], py2[OPT], pz2[OPT];
        float rq[OPT], mn[OPT];
#pragma unroll
        for (int o = 0; o < OPT; o++) {
            int i = gbase + o * T + tid;
            float x = outer[3*i], y = outer[3*i+1], z = outer[3*i+2];
            px2[o] = pk(x, x); py2[o] = pk(y, y); pz2[o] = pk(z, z);
            rq[o]  = fmaf(x, x, fmaf(y, y, z*z));
            mn[o]  = FLT_MAX;
        }

        // LB part 1: candidate vs all inner (8 evals/thread from L2)
        float cm = FLT_MAX;
#pragma unroll
        for (int k = 0; k < NPTS / T; k++) {
            float4 p = packp[tid + k * T];
            float t = fmaf(p.x, cand.x, p.w);
            t = fmaf(p.y, cand.y, t);
            t = fmaf(p.z, cand.z, t);
            cm = fminf(cm, t);
        }
        __syncthreads();                              // staging visible

        // branchless phase-1 scan (128 slots = 256 pts)
#pragma unroll 8
        for (int s = 0; s < P1SLOTS; s++) {
            ulonglong2 ab = shv[s * 2 + 0];
            ulonglong2 cd = shv[s * 2 + 1];
#pragma unroll
            for (int o = 0; o < OPT; o++) {
                u64t t = fma2(ab.x, px2[o], cd.y);
                t = fma2(ab.y, py2[o], t);
                t = fma2(cd.x, pz2[o], t);
                float2 tv = upk(t);
                mn[o] = fminf(mn[o], fminf(tv.x, tv.y));
            }
        }

        // LB part 2: reduce -> LB with margin
#pragma unroll
        for (int off = 16; off; off >>= 1)
            cm = fminf(cm, __shfl_xor_sync(0xffffffffu, cm, off));
        if ((tid & 31) == 0) s_red[tid >> 5] = cm;
        __syncthreads();
        if (tid == 0) {
            float m = s_red[0];
#pragma unroll
            for (int w = 1; w < T / 32; w++) m = fminf(m, s_red[w]);
            float lb = m + cand.w;
            s_lb = lb - fabsf(lb) * 1e-5f - 1e-12f;
            if (och == 0) g_lb[dir][b] = s_lb;       // identical in all blocks
        }
        __syncthreads();

        // filter: certified -> block max; uncertified -> global list
        const float lbm = s_lb;
        float cmax = -FLT_MAX;
#pragma unroll
        for (int o = 0; o < OPT; o++) {
            int gi = gbase + o * T + tid;
            float v = mn[o] + rq[o];
            if (v < lbm) {
                cmax = fmaxf(cmax, v);
            } else {
                int k = atomicAdd(&g_cnt, 1);
                g_list[k] = make_int2((dir << 16) | (b << 12) | gi,
                                      __float_as_int(v));
            }
        }
#pragma unroll
        for (int off = 16; off; off >>= 1)
            cmax = fmaxf(cmax, __shfl_xor_sync(0xffffffffu, cmax, off));
        if ((tid & 31) == 0) s_red[tid >> 5] = cmax;
        __syncthreads();
        if (tid == 0) {
            float m = s_red[0];
#pragma unroll
            for (int w = 1; w < T / 32; w++) m = fmaxf(m, s_red[w]);
            atomicMax(&g_bmax_u[dir][b], encf(m));
        }
    }
    gbar(1);

    // ================= Phase C: warp-per-point tail =========================
    {
        const int wgid = bid * (T / 32) + (tid >> 5);
        const int cnt  = g_cnt;

        for (int u = wgid; u < cnt; u += NBLK * (T / 32)) {
            const int2 e = g_list[u];
            const int code = e.x;
            const float partial = __int_as_float(e.y);
            const int gi = code & 4095, b = (code >> 12) & 15, dir = code >> 16;
            const float* __restrict__ outer = (dir == 0 ? preds : gts) + (size_t)b * NPTS * 3;

            const float x = outer[3*gi], y = outer[3*gi+1], z = outer[3*gi+2];
            const float rq = fmaf(x, x, fmaf(y, y, z*z));
            const float thr = g_lb[dir][b] - rq;     // s-domain threshold
            const float4* packp = &g_pack[dir ^ 1][b][0];

            float m = FLT_MAX;
            // [P1PTS, NPTS) = 3840 pts = 15 rounds of 256 (divides evenly)
            for (int base = P1PTS; base < NPTS; base += 32 * VC) {
#pragma unroll
                for (int k = 0; k < VC; k++) {
                    float4 p = packp[base + k * 32 + lane];
                    float t = fmaf(p.x, x, p.w);
                    t = fmaf(p.y, y, t);
                    t = fmaf(p.z, z, t);
                    m = fminf(m, t);
                }
                if (__any_sync(0xffffffffu, m < thr)) break;   // certified
            }
#pragma unroll
            for (int off = 16; off; off >>= 1)
                m = fminf(m, __shfl_xor_sync(0xffffffffu, m, off));
            if (lane == 0)
                atomicMax(&g_bmax_u[dir][b], encf(fminf(partial, m + rq)));
        }
    }
    gbar(2);

    // ================= final: block 0 writes out ============================
    if (bid == 0 && tid < BATCH) {
        float l2 = decf(atomicAdd(&g_bmax_u[0][tid], 0u));
        float l1 = decf(atomicAdd(&g_bmax_u[1][tid], 0u));
        out[tid] = 0.5f * (l1 + l2);
    }
}

extern "C" void kernel_launch(void* const* d_in, const int* in_sizes, int n_in,
                              void* d_out, int out_size) {
    const float* preds = (const float*)d_in[0];
    const float* gts   = (const float*)d_in[1];
    float* out = (float*)d_out;

    hd_fused<<<NBLK, T>>>(preds, gts, out);
}

// round 14
// speedup vs baseline: 1.1782x; 1.0449x over previous
#include <cuda_runtime.h>
#include <cfloat>

// Symmetric squared-Hausdorff per batch — single persistent kernel (R14).
// d^2(p,g) = |p|^2 + s, s = |g|^2 - 2 p.g (|p|^2 added after the min).
//
// Grid = 128 blocks x 512 threads (1 block/SM, all co-resident).
// Phase A: pack both arrays (-2g,|g|^2) + per-chunk radius-argmax + resets.
//          [grid barrier]
// Phase B: per (dir,b,och): candidate = best of 4 chunk candidates; each
//          block scans ITS QUARTER of the opposite pack for the candidate min
//          (atomicMin-combined, 4-way distributed LB); branchless f32x2 scan
//          of first 256 inner pts; after p1, poll LB-arrival counter (==4),
//          filter: certified -> block max atomicMax; uncertified -> list.
//          [grid barrier]
// Phase C: warps WORK-STEAL list entries (atomic ticket); one point/warp over
//          remaining 3840 inner pts (15 x 256-pt vote rounds, even split);
//          exact values atomicMax'ed. Done-ticket: last block writes out[16].
//
// Exactness: certified partials lie in [true, LB) and cannot win the max;
// the argmax never certifies and its exact min is computed from identically-
// evaluated per-pair values. All combines (min/max/atomicMin/atomicMax) are
// order-independent -> deterministic.

#define BATCH   16
#define NPTS    4096
#define NBLK    128
#define T       512
#define PCH     4                    // pack chunks per (arr,b)
#define OPT     2
#define PTSBLK  (T * OPT)            // 1024 outer pts per phase-B block
#define OCH     4
#define P1PTS   256                  // phase-1 inner points
#define P1SLOTS (P1PTS / 2)          // 128 packed pair-slots
#define VC      8                    // tail lane-iters per vote round (256 pts)

__device__ float4       g_pack[2][BATCH][NPTS];     // (-2gx,-2gy,-2gz,|g|^2)
__device__ float4       g_candpart[2][BATCH][PCH];  // (cx,cy,cz,|c|^2)
__device__ unsigned int g_lbmin_u[2][BATCH];        // encoded min (s-domain)
__device__ unsigned int g_lbc[2][BATCH];            // LB arrival counter
__device__ float        g_lb[2][BATCH];             // final LB (with margin)
__device__ int2         g_list[2 * BATCH * NPTS];   // (code, partial bits)
__device__ int          g_cnt;
__device__ int          g_ticket;
__device__ unsigned int g_done;
__device__ unsigned int g_bar[2];                   // generation barriers
__device__ unsigned int g_bmax_u[2][BATCH];         // monotonic-encoded max

typedef unsigned long long u64t;

__device__ __forceinline__ u64t fma2(u64t a, u64t b, u64t c) {
    u64t d;
    asm("fma.rn.f32x2 %0, %1, %2, %3;" : "=l"(d) : "l"(a), "l"(b), "l"(c));
    return d;
}
__device__ __forceinline__ u64t pk(float lo, float hi) {
    u64t d;
    asm("mov.b64 %0, {%1, %2};" : "=l"(d) : "f"(lo), "f"(hi));
    return d;
}
__device__ __forceinline__ float2 upk(u64t v) {
    float2 r;
    asm("mov.b64 {%0, %1}, %2;" : "=f"(r.x), "=f"(r.y) : "l"(v));
    return r;
}
// monotonic float<->uint (total order preserved under unsigned compare)
__device__ __forceinline__ unsigned int encf(float v) {
    unsigned int b = __float_as_uint(v);
    return (b & 0x80000000u) ? ~b : (b | 0x80000000u);
}
__device__ __forceinline__ float decf(unsigned int u) {
    unsigned int b = (u & 0x80000000u) ? (u & 0x7fffffffu) : ~u;
    return __uint_as_float(b);
}
__device__ __forceinline__ unsigned int ldacq(const unsigned int* p) {
    unsigned int v;
    asm volatile("ld.acquire.gpu.u32 %0, [%1];" : "=r"(v) : "l"(p) : "memory");
    return v;
}

// generation-counting grid barrier; poll is a plain acquire load (no atomic-
// ALU serialization). Counter is monotonic -> safe across graph replays.
__device__ __forceinline__ void gbar(int which) {
    __threadfence();
    __syncthreads();
    if (threadIdx.x == 0) {
        unsigned int gen = atomicAdd(&g_bar[which], 1u) / NBLK;
        while (ldacq(&g_bar[which]) / NBLK == gen) { }
    }
    __syncthreads();
}

__global__ void __launch_bounds__(T, 1)
hd_fused(const float* __restrict__ preds, const float* __restrict__ gts,
         float* __restrict__ out) {
    __shared__ __align__(16) ulonglong2 shv[P1SLOTS * 2];   // 4 KB
    __shared__ float s_red[T / 32];
    __shared__ int   s_redi[T / 32];
    __shared__ float s_lb;
    __shared__ bool  s_last;

    const int bid = blockIdx.x;
    const int tid = threadIdx.x;
    const int lane = tid & 31;

    // ================= Phase A: pack + chunk candidates + resets ===========
    {
        const int arr = bid >> 6, b = (bid >> 2) & 15, ch = bid & 3;
        const float* __restrict__ src = (arr == 0 ? preds : gts) + (size_t)b * NPTS * 3;
        const int base = ch * (NPTS / PCH);          // 1024 pts / block

        if (tid == 0 && ch == 0) {
            g_bmax_u[arr][b]  = 0u;
            g_lbmin_u[arr][b] = 0xFFFFFFFFu;
            g_lbc[arr][b]     = 0u;
            if (bid == 0) { g_cnt = 0; g_ticket = 0; g_done = 0u; }
        }

        float4* packp = &g_pack[arr][b][0];
        float bestr = -1.0f; int besti = 0;
#pragma unroll
        for (int k = 0; k < NPTS / PCH / T; k++) {   // 2 points/thread
            int j = base + tid + k * T;
            float gx = src[3*j], gy = src[3*j+1], gz = src[3*j+2];
            float w  = fmaf(gx, gx, fmaf(gy, gy, gz * gz));
            packp[j] = make_float4(-2.0f*gx, -2.0f*gy, -2.0f*gz, w);
            if (w > bestr || (w == bestr && j < besti)) { bestr = w; besti = j; }
        }
#pragma unroll
        for (int off = 16; off; off >>= 1) {
            float r2 = __shfl_xor_sync(0xffffffffu, bestr, off);
            int   i2 = __shfl_xor_sync(0xffffffffu, besti, off);
            if (r2 > bestr || (r2 == bestr && i2 < besti)) { bestr = r2; besti = i2; }
        }
        if ((tid & 31) == 0) { s_red[tid>>5] = bestr; s_redi[tid>>5] = besti; }
        __syncthreads();
        if (tid == 0) {
            float r = s_red[0]; int i = s_redi[0];
#pragma unroll
            for (int w = 1; w < T/32; w++)
                if (s_red[w] > r || (s_red[w] == r && s_redi[w] < i)) { r = s_red[w]; i = s_redi[w]; }
            g_candpart[arr][b][ch] = make_float4(src[3*i], src[3*i+1], src[3*i+2], r);
        }
        __syncthreads();
    }
    gbar(0);

    // ================= Phase B: distributed LB + branchless p1 + filter =====
    {
        const int dir = bid >> 6, b = (bid >> 2) & 15, och = bid & 3;
        const float* __restrict__ outer = (dir == 0 ? preds : gts) + (size_t)b * NPTS * 3;
        const float* __restrict__ inner = (dir == 0 ? gts : preds) + (size_t)b * NPTS * 3;
        const float4* __restrict__ packp = &g_pack[dir ^ 1][b][0];

        // stage first P1SLOTS pairs
        if (tid < P1SLOTS) {
            const float* gp = inner + (size_t)tid * 6;
            float x0 = gp[0], y0 = gp[1], z0 = gp[2];
            float x1 = gp[3], y1 = gp[4], z1 = gp[5];
            ((float4*)shv)[tid * 2 + 0] = make_float4(-2.f*x0, -2.f*x1, -2.f*y0, -2.f*y1);
            ((float4*)shv)[tid * 2 + 1] = make_float4(-2.f*z0, -2.f*z1,
                                    fmaf(x0, x0, fmaf(y0, y0, z0*z0)),
                                    fmaf(x1, x1, fmaf(y1, y1, z1*z1)));
        }

        // candidate = best of 4 chunk candidates (deterministic ascending scan)
        float4 cand = g_candpart[dir][b][0];
#pragma unroll
        for (int c = 1; c < PCH; c++) {
            float4 q = g_candpart[dir][b][c];
            if (q.w > cand.w) cand = q;
        }

        const int gbase = och * PTSBLK;
        u64t px2[OPT], py2[OPT], pz2[OPT];
        float rq[OPT], mn[OPT];
#pragma unroll
        for (int o = 0; o < OPT; o++) {
            int i = gbase + o * T + tid;
            float x = outer[3*i], y = outer[3*i+1], z = outer[3*i+2];
            px2[o] = pk(x, x); py2[o] = pk(y, y); pz2[o] = pk(z, z);
            rq[o]  = fmaf(x, x, fmaf(y, y, z*z));
            mn[o]  = FLT_MAX;
        }

        // distributed LB: candidate vs THIS BLOCK'S QUARTER of the inner pack
        float cm = FLT_MAX;
#pragma unroll
        for (int k = 0; k < PTSBLK / T; k++) {       // 2 evals/thread
            float4 p = packp[och * PTSBLK + tid + k * T];
            float t = fmaf(p.x, cand.x, p.w);
            t = fmaf(p.y, cand.y, t);
            t = fmaf(p.z, cand.z, t);
            cm = fminf(cm, t);
        }
#pragma unroll
        for (int off = 16; off; off >>= 1)
            cm = fminf(cm, __shfl_xor_sync(0xffffffffu, cm, off));
        if ((tid & 31) == 0) s_red[tid >> 5] = cm;
        __syncthreads();                              // also: staging visible
        if (tid == 0) {
            float m = s_red[0];
#pragma unroll
            for (int w = 1; w < T / 32; w++) m = fminf(m, s_red[w]);
            atomicMin(&g_lbmin_u[dir][b], encf(m));
            __threadfence();
            atomicAdd(&g_lbc[dir][b], 1u);
        }

        // branchless phase-1 scan (128 slots = 256 pts)
#pragma unroll 8
        for (int s = 0; s < P1SLOTS; s++) {
            ulonglong2 ab = shv[s * 2 + 0];
            ulonglong2 cd = shv[s * 2 + 1];
#pragma unroll
            for (int o = 0; o < OPT; o++) {
                u64t t = fma2(ab.x, px2[o], cd.y);
                t = fma2(ab.y, py2[o], t);
                t = fma2(cd.x, pz2[o], t);
                float2 tv = upk(t);
                mn[o] = fminf(mn[o], fminf(tv.x, tv.y));
            }
        }

        // collect the combined LB (all 4 contributions normally long done)
        if (tid == 0) {
            while (ldacq(&g_lbc[dir][b]) < OCH) { }
            float lb = decf(ldacq(&g_lbmin_u[dir][b])) + cand.w;
            s_lb = lb - fabsf(lb) * 1e-5f - 1e-12f;
            if (och == 0) g_lb[dir][b] = s_lb;       // identical in all blocks
        }
        __syncthreads();

        // filter: certified -> block max; uncertified -> global list
        const float lbm = s_lb;
        float cmax = -FLT_MAX;
#pragma unroll
        for (int o = 0; o < OPT; o++) {
            int gi = gbase + o * T + tid;
            float v = mn[o] + rq[o];
            if (v < lbm) {
                cmax = fmaxf(cmax, v);
            } else {
                int k = atomicAdd(&g_cnt, 1);
                g_list[k] = make_int2((dir << 16) | (b << 12) | gi,
                                      __float_as_int(v));
            }
        }
#pragma unroll
        for (int off = 16; off; off >>= 1)
            cmax = fmaxf(cmax, __shfl_xor_sync(0xffffffffu, cmax, off));
        if ((tid & 31) == 0) s_red[tid >> 5] = cmax;
        __syncthreads();
        if (tid == 0) {
            float m = s_red[0];
#pragma unroll
            for (int w = 1; w < T / 32; w++) m = fmaxf(m, s_red[w]);
            atomicMax(&g_bmax_u[dir][b], encf(m));
        }
    }
    gbar(1);

    // ================= Phase C: work-stealing warp-per-point tail ===========
    {
        const int cnt = g_cnt;
        int u;
        if (lane == 0) u = atomicAdd(&g_ticket, 1);
        u = __shfl_sync(0xffffffffu, u, 0);
        while (u < cnt) {
            const int2 e = g_list[u];
            const int code = e.x;
            const float partial = __int_as_float(e.y);
            const int gi = code & 4095, b = (code >> 12) & 15, dir = code >> 16;
            const float* __restrict__ outer = (dir == 0 ? preds : gts) + (size_t)b * NPTS * 3;

            const float x = outer[3*gi], y = outer[3*gi+1], z = outer[3*gi+2];
            const float rq = fmaf(x, x, fmaf(y, y, z*z));
            const float thr = g_lb[dir][b] - rq;     // s-domain threshold
            const float4* packp = &g_pack[dir ^ 1][b][0];

            float m = FLT_MAX;
            // [P1PTS, NPTS) = 3840 pts = 15 rounds of 256 (divides evenly)
            for (int base = P1PTS; base < NPTS; base += 32 * VC) {
#pragma unroll
                for (int k = 0; k < VC; k++) {
                    float4 p = packp[base + k * 32 + lane];
                    float t = fmaf(p.x, x, p.w);
                    t = fmaf(p.y, y, t);
                    t = fmaf(p.z, z, t);
                    m = fminf(m, t);
                }
                if (__any_sync(0xffffffffu, m < thr)) break;   // certified
            }
#pragma unroll
            for (int off = 16; off; off >>= 1)
                m = fminf(m, __shfl_xor_sync(0xffffffffu, m, off));
            if (lane == 0)
                atomicMax(&g_bmax_u[dir][b], encf(fminf(partial, m + rq)));

            if (lane == 0) u = atomicAdd(&g_ticket, 1);
            u = __shfl_sync(0xffffffffu, u, 0);
        }
    }

    // ================= done-ticket final: last block writes out =============
    __threadfence();
    __syncthreads();
    if (tid == 0) {
        unsigned int t = atomicAdd(&g_done, 1u);
        s_last = ((t % NBLK) == NBLK - 1);
    }
    __syncthreads();
    if (s_last && tid < BATCH) {
        float l2 = decf(ldacq(&g_bmax_u[0][tid]));
        float l1 = decf(ldacq(&g_bmax_u[1][tid]));
        out[tid] = 0.5f * (l1 + l2);
    }
}

extern "C" void kernel_launch(void* const* d_in, const int* in_sizes, int n_in,
                              void* d_out, int out_size) {
    const float* preds = (const float*)d_in[0];
    const float* gts   = (const float*)d_in[1];
    float* out = (float*)d_out;

    hd_fused<<<NBLK, T>>>(preds, gts, out);
}

// round 15
// speedup vs baseline: 1.2641x; 1.0729x over previous
#include <cuda_runtime.h>
#include <cfloat>

// Symmetric squared-Hausdorff per batch — single persistent kernel (R15).
// d^2(p,g) = |p|^2 + s, s = |g|^2 - 2 p.g (|p|^2 added after the min).
//
// Grid = 128 blocks x 512 threads (1 block/SM, all co-resident).
// Phase A: pack both arrays (-2g,|g|^2) + per-chunk radius-argmax + resets.
//          [grid barrier]
// Phase B: per (dir,b,och): candidate = best of 4 chunk candidates; each
//          block scans its quarter of the opposite pack for the candidate min
//          (atomicMin-combined distributed LB); branchless f32x2 scan of the
//          FIRST 128 inner pts; poll LB counter; certified -> block max
//          atomicMax; uncertified -> global list.
//          [grid barrier]
// Phase C: warps work-steal list entries (atomic ticket); one point/warp:
//          half-round [128,256) (4 lane-iters + vote), then 15 x 256-pt vote
//          rounds over [256,4096) (divides evenly — no OOB); exact values
//          atomicMax'ed. Done-ticket: last block writes out[16].
//
// Exactness: certified partials lie in [true, LB) and cannot win the max;
// the argmax never certifies and its exact min is computed from identically-
// evaluated per-pair values. All combines (min/max/atomicMin/atomicMax) are
// order-independent -> deterministic.

#define BATCH   16
#define NPTS    4096
#define NBLK    128
#define T       512
#define PCH     4                    // pack chunks per (arr,b)
#define OPT     2
#define PTSBLK  (T * OPT)            // 1024 outer pts per phase-B block
#define OCH     4
#define P1PTS   128                  // phase-1 inner points
#define P1SLOTS (P1PTS / 2)          // 64 packed pair-slots
#define TAIL0   256                  // start of evenly-divisible tail region
#define VC      8                    // tail lane-iters per vote round (256 pts)

__device__ float4       g_pack[2][BATCH][NPTS];     // (-2gx,-2gy,-2gz,|g|^2)
__device__ float4       g_candpart[2][BATCH][PCH];  // (cx,cy,cz,|c|^2)
__device__ unsigned int g_lbmin_u[2][BATCH];        // encoded min (s-domain)
__device__ unsigned int g_lbc[2][BATCH];            // LB arrival counter
__device__ float        g_lb[2][BATCH];             // final LB (with margin)
__device__ int2         g_list[2 * BATCH * NPTS];   // (code, partial bits)
__device__ int          g_cnt;
__device__ int          g_ticket;
__device__ unsigned int g_done;
__device__ unsigned int g_bar[2];                   // generation barriers
__device__ unsigned int g_bmax_u[2][BATCH];         // monotonic-encoded max

typedef unsigned long long u64t;

__device__ __forceinline__ u64t fma2(u64t a, u64t b, u64t c) {
    u64t d;
    asm("fma.rn.f32x2 %0, %1, %2, %3;" : "=l"(d) : "l"(a), "l"(b), "l"(c));
    return d;
}
__device__ __forceinline__ u64t pk(float lo, float hi) {
    u64t d;
    asm("mov.b64 %0, {%1, %2};" : "=l"(d) : "f"(lo), "f"(hi));
    return d;
}
__device__ __forceinline__ float2 upk(u64t v) {
    float2 r;
    asm("mov.b64 {%0, %1}, %2;" : "=f"(r.x), "=f"(r.y) : "l"(v));
    return r;
}
// monotonic float<->uint (total order preserved under unsigned compare)
__device__ __forceinline__ unsigned int encf(float v) {
    unsigned int b = __float_as_uint(v);
    return (b & 0x80000000u) ? ~b : (b | 0x80000000u);
}
__device__ __forceinline__ float decf(unsigned int u) {
    unsigned int b = (u & 0x80000000u) ? (u & 0x7fffffffu) : ~u;
    return __uint_as_float(b);
}
__device__ __forceinline__ unsigned int ldacq(const unsigned int* p) {
    unsigned int v;
    asm volatile("ld.acquire.gpu.u32 %0, [%1];" : "=r"(v) : "l"(p) : "memory");
    return v;
}

// generation-counting grid barrier; poll is a plain acquire load (no atomic-
// ALU serialization). Counter is monotonic -> safe across graph replays.
__device__ __forceinline__ void gbar(int which) {
    __threadfence();
    __syncthreads();
    if (threadIdx.x == 0) {
        unsigned int gen = atomicAdd(&g_bar[which], 1u) / NBLK;
        while (ldacq(&g_bar[which]) / NBLK == gen) { }
    }
    __syncthreads();
}

__global__ void __launch_bounds__(T, 1)
hd_fused(const float* __restrict__ preds, const float* __restrict__ gts,
         float* __restrict__ out) {
    __shared__ __align__(16) ulonglong2 shv[P1SLOTS * 2];   // 2 KB
    __shared__ float s_red[T / 32];
    __shared__ int   s_redi[T / 32];
    __shared__ float s_lb;
    __shared__ bool  s_last;

    const int bid = blockIdx.x;
    const int tid = threadIdx.x;
    const int lane = tid & 31;

    // ================= Phase A: pack + chunk candidates + resets ===========
    {
        const int arr = bid >> 6, b = (bid >> 2) & 15, ch = bid & 3;
        const float* __restrict__ src = (arr == 0 ? preds : gts) + (size_t)b * NPTS * 3;
        const int base = ch * (NPTS / PCH);          // 1024 pts / block

        if (tid == 0 && ch == 0) {
            g_bmax_u[arr][b]  = 0u;
            g_lbmin_u[arr][b] = 0xFFFFFFFFu;
            g_lbc[arr][b]     = 0u;
            if (bid == 0) { g_cnt = 0; g_ticket = 0; g_done = 0u; }
        }

        float4* packp = &g_pack[arr][b][0];
        float bestr = -1.0f; int besti = 0;
#pragma unroll
        for (int k = 0; k < NPTS / PCH / T; k++) {   // 2 points/thread
            int j = base + tid + k * T;
            float gx = src[3*j], gy = src[3*j+1], gz = src[3*j+2];
            float w  = fmaf(gx, gx, fmaf(gy, gy, gz * gz));
            packp[j] = make_float4(-2.0f*gx, -2.0f*gy, -2.0f*gz, w);
            if (w > bestr || (w == bestr && j < besti)) { bestr = w; besti = j; }
        }
#pragma unroll
        for (int off = 16; off; off >>= 1) {
            float r2 = __shfl_xor_sync(0xffffffffu, bestr, off);
            int   i2 = __shfl_xor_sync(0xffffffffu, besti, off);
            if (r2 > bestr || (r2 == bestr && i2 < besti)) { bestr = r2; besti = i2; }
        }
        if ((tid & 31) == 0) { s_red[tid>>5] = bestr; s_redi[tid>>5] = besti; }
        __syncthreads();
        if (tid == 0) {
            float r = s_red[0]; int i = s_redi[0];
#pragma unroll
            for (int w = 1; w < T/32; w++)
                if (s_red[w] > r || (s_red[w] == r && s_redi[w] < i)) { r = s_red[w]; i = s_redi[w]; }
            g_candpart[arr][b][ch] = make_float4(src[3*i], src[3*i+1], src[3*i+2], r);
        }
        __syncthreads();
    }
    gbar(0);

    // ================= Phase B: distributed LB + branchless p1 + filter =====
    {
        const int dir = bid >> 6, b = (bid >> 2) & 15, och = bid & 3;
        const float* __restrict__ outer = (dir == 0 ? preds : gts) + (size_t)b * NPTS * 3;
        const float* __restrict__ inner = (dir == 0 ? gts : preds) + (size_t)b * NPTS * 3;
        const float4* __restrict__ packp = &g_pack[dir ^ 1][b][0];

        // stage first P1SLOTS pairs
        if (tid < P1SLOTS) {
            const float* gp = inner + (size_t)tid * 6;
            float x0 = gp[0], y0 = gp[1], z0 = gp[2];
            float x1 = gp[3], y1 = gp[4], z1 = gp[5];
            ((float4*)shv)[tid * 2 + 0] = make_float4(-2.f*x0, -2.f*x1, -2.f*y0, -2.f*y1);
            ((float4*)shv)[tid * 2 + 1] = make_float4(-2.f*z0, -2.f*z1,
                                    fmaf(x0, x0, fmaf(y0, y0, z0*z0)),
                                    fmaf(x1, x1, fmaf(y1, y1, z1*z1)));
        }

        // candidate = best of 4 chunk candidates (deterministic ascending scan)
        float4 cand = g_candpart[dir][b][0];
#pragma unroll
        for (int c = 1; c < PCH; c++) {
            float4 q = g_candpart[dir][b][c];
            if (q.w > cand.w) cand = q;
        }

        const int gbase = och * PTSBLK;
        u64t px2[OPT], py2[OPT], pz2[OPT];
        float rq[OPT], mn[OPT];
#pragma unroll
        for (int o = 0; o < OPT; o++) {
            int i = gbase + o * T + tid;
            float x = outer[3*i], y = outer[3*i+1], z = outer[3*i+2];
            px2[o] = pk(x, x); py2[o] = pk(y, y); pz2[o] = pk(z, z);
            rq[o]  = fmaf(x, x, fmaf(y, y, z*z));
            mn[o]  = FLT_MAX;
        }

        // distributed LB: candidate vs THIS BLOCK'S QUARTER of the inner pack
        float cm = FLT_MAX;
#pragma unroll
        for (int k = 0; k < PTSBLK / T; k++) {       // 2 evals/thread
            float4 p = packp[och * PTSBLK + tid + k * T];
            float t = fmaf(p.x, cand.x, p.w);
            t = fmaf(p.y, cand.y, t);
            t = fmaf(p.z, cand.z, t);
            cm = fminf(cm, t);
        }
#pragma unroll
        for (int off = 16; off; off >>= 1)
            cm = fminf(cm, __shfl_xor_sync(0xffffffffu, cm, off));
        if ((tid & 31) == 0) s_red[tid >> 5] = cm;
        __syncthreads();                              // also: staging visible
        if (tid == 0) {
            float m = s_red[0];
#pragma unroll
            for (int w = 1; w < T / 32; w++) m = fminf(m, s_red[w]);
            atomicMin(&g_lbmin_u[dir][b], encf(m));
            __threadfence();
            atomicAdd(&g_lbc[dir][b], 1u);
        }

        // branchless phase-1 scan (64 slots = 128 pts)
#pragma unroll 8
        for (int s = 0; s < P1SLOTS; s++) {
            ulonglong2 ab = shv[s * 2 + 0];
            ulonglong2 cd = shv[s * 2 + 1];
#pragma unroll
            for (int o = 0; o < OPT; o++) {
                u64t t = fma2(ab.x, px2[o], cd.y);
                t = fma2(ab.y, py2[o], t);
                t = fma2(cd.x, pz2[o], t);
                float2 tv = upk(t);
                mn[o] = fminf(mn[o], fminf(tv.x, tv.y));
            }
        }

        // collect the combined LB (all 4 contributions normally long done)
        if (tid == 0) {
            while (ldacq(&g_lbc[dir][b]) < OCH) { }
            float lb = decf(ldacq(&g_lbmin_u[dir][b])) + cand.w;
            s_lb = lb - fabsf(lb) * 1e-5f - 1e-12f;
            if (och == 0) g_lb[dir][b] = s_lb;       // identical in all blocks
        }
        __syncthreads();

        // filter: certified -> block max; uncertified -> global list
        const float lbm = s_lb;
        float cmax = -FLT_MAX;
#pragma unroll
        for (int o = 0; o < OPT; o++) {
            int gi = gbase + o * T + tid;
            float v = mn[o] + rq[o];
            if (v < lbm) {
                cmax = fmaxf(cmax, v);
            } else {
                int k = atomicAdd(&g_cnt, 1);
                g_list[k] = make_int2((dir << 16) | (b << 12) | gi,
                                      __float_as_int(v));
            }
        }
#pragma unroll
        for (int off = 16; off; off >>= 1)
            cmax = fmaxf(cmax, __shfl_xor_sync(0xffffffffu, cmax, off));
        if ((tid & 31) == 0) s_red[tid >> 5] = cmax;
        __syncthreads();
        if (tid == 0) {
            float m = s_red[0];
#pragma unroll
            for (int w = 1; w < T / 32; w++) m = fmaxf(m, s_red[w]);
            atomicMax(&g_bmax_u[dir][b], encf(m));
        }
    }
    gbar(1);

    // ================= Phase C: work-stealing warp-per-point tail ===========
    {
        const int cnt = g_cnt;
        int u;
        if (lane == 0) u = atomicAdd(&g_ticket, 1);
        u = __shfl_sync(0xffffffffu, u, 0);
        while (u < cnt) {
            const int2 e = g_list[u];
            const int code = e.x;
            const float partial = __int_as_float(e.y);
            const int gi = code & 4095, b = (code >> 12) & 15, dir = code >> 16;
            const float* __restrict__ outer = (dir == 0 ? preds : gts) + (size_t)b * NPTS * 3;

            const float x = outer[3*gi], y = outer[3*gi+1], z = outer[3*gi+2];
            const float rq = fmaf(x, x, fmaf(y, y, z*z));
            const float thr = g_lb[dir][b] - rq;     // s-domain threshold
            const float4* packp = &g_pack[dir ^ 1][b][0];

            float m = FLT_MAX;
            // half round: inner points [P1PTS, TAIL0) = 128 pts (4 lane-iters)
#pragma unroll
            for (int k = 0; k < (TAIL0 - P1PTS) / 32; k++) {
                float4 p = packp[P1PTS + k * 32 + lane];
                float t = fmaf(p.x, x, p.w);
                t = fmaf(p.y, y, t);
                t = fmaf(p.z, z, t);
                m = fminf(m, t);
            }
            if (!__any_sync(0xffffffffu, m < thr)) {
                // full rounds: [TAIL0, NPTS) = 3840 pts = 15 rounds of 256
                for (int base = TAIL0; base < NPTS; base += 32 * VC) {
#pragma unroll
                    for (int k = 0; k < VC; k++) {
                        float4 p = packp[base + k * 32 + lane];
                        float t = fmaf(p.x, x, p.w);
                        t = fmaf(p.y, y, t);
                        t = fmaf(p.z, z, t);
                        m = fminf(m, t);
                    }
                    if (__any_sync(0xffffffffu, m < thr)) break;   // certified
                }
            }
#pragma unroll
            for (int off = 16; off; off >>= 1)
                m = fminf(m, __shfl_xor_sync(0xffffffffu, m, off));
            if (lane == 0)
                atomicMax(&g_bmax_u[dir][b], encf(fminf(partial, m + rq)));

            if (lane == 0) u = atomicAdd(&g_ticket, 1);
            u = __shfl_sync(0xffffffffu, u, 0);
        }
    }

    // ================= done-ticket final: last block writes out =============
    __threadfence();
    __syncthreads();
    if (tid == 0) {
        unsigned int t = atomicAdd(&g_done, 1u);
        s_last = ((t % NBLK) == NBLK - 1);
    }
    __syncthreads();
    if (s_last && tid < BATCH) {
        float l2 = decf(ldacq(&g_bmax_u[0][tid]));
        float l1 = decf(ldacq(&g_bmax_u[1][tid]));
        out[tid] = 0.5f * (l1 + l2);
    }
}

extern "C" void kernel_launch(void* const* d_in, const int* in_sizes, int n_in,
                              void* d_out, int out_size) {
    const float* preds = (const float*)d_in[0];
    const float* gts   = (const float*)d_in[1];
    float* out = (float*)d_out;

    hd_fused<<<NBLK, T>>>(preds, gts, out);
}